// round 17
// baseline (speedup 1.0000x reference)
#include <cuda_runtime.h>

#define BB   4
#define NN   8000
#define CC   64
#define KK   32
#define DD   9
#define NCLS 13
#define BN   (BB*NN)

#define NB    256         // x-buckets per batch
#define CAPA  56          // append slots per thread (smem)
#define NSLOT (KK + CAPA) // 88 u64 slots per thread

__device__ float  g_G1[BN*CC];
__device__ float  g_G2[BN*CC];
__device__ float4 g_pts[BN];
__device__ int    g_idx[BN*KK];
__device__ float  g_C1[CC*CC], g_C2[CC*CC], g_c1[CC], g_c2[CC];
__device__ float4 g_sorted[BN];
__device__ int    g_sidx[BN];
__device__ int    g_bstart[BB][NB+1];
__device__ int    g_bcur[BB][NB];
__device__ float2 g_bparam[BB];        // (xmin, w)

__device__ __forceinline__ float inf_f() { return __int_as_float(0x7f800000); }
__device__ __forceinline__ float nan_f() { return __int_as_float(0x7fffffff); }

// ---------------------------------------------------------------------------
// Precompute: C1 = w2@f1w, C2 = w2@f2w, c1 = b2@f1w, c2 = b2@f2w.
// ---------------------------------------------------------------------------
__global__ __launch_bounds__(256) void precompute_kernel(
    const float* __restrict__ w2, const float* __restrict__ b2v,
    const float* __restrict__ f1w, const float* __restrict__ f2w)
{
    int idx = blockIdx.x*256 + threadIdx.x;
    if (idx < CC*CC) {
        int r = idx / CC, c = idx % CC;
        float a = 0.f;
        #pragma unroll 4
        for (int k = 0; k < CC; k++) a = fmaf(w2[r*CC+k], f1w[k*CC+c], a);
        g_C1[idx] = a;
    } else if (idx < 2*CC*CC) {
        int t = idx - CC*CC;
        int r = t / CC, c = t % CC;
        float a = 0.f;
        #pragma unroll 4
        for (int k = 0; k < CC; k++) a = fmaf(w2[r*CC+k], f2w[k*CC+c], a);
        g_C2[t] = a;
    } else if (idx < 2*CC*CC + CC) {
        int c = idx - 2*CC*CC;
        float a = 0.f;
        #pragma unroll 4
        for (int k = 0; k < CC; k++) a = fmaf(b2v[k], f1w[k*CC+c], a);
        g_c1[c] = a;
    } else if (idx < 2*CC*CC + 2*CC) {
        int c = idx - 2*CC*CC - CC;
        float a = 0.f;
        #pragma unroll 4
        for (int k = 0; k < CC; k++) a = fmaf(b2v[k], f2w[k*CC+c], a);
        g_c2[c] = a;
    }
}

// ---------------------------------------------------------------------------
// Encoder (R14, measured-best): hidden = relu(x@w1+b1) -> strided smem;
// G1 = hidden@C1 + c1 ; G2 = hidden@C2 + c2.
// ---------------------------------------------------------------------------
__global__ __launch_bounds__(256) void encoder_kernel(
    const float* __restrict__ x,
    const float* __restrict__ w1, const float* __restrict__ b1v)
{
    extern __shared__ float sh[];
    int tid = threadIdx.x;
    int g = blockIdx.x*256 + tid;
    if (g >= BN) return;

    float xr[DD];
    #pragma unroll
    for (int d = 0; d < DD; d++) xr[d] = x[g*DD + d];
    g_pts[g] = make_float4(xr[0], xr[1], xr[2],
                           xr[0]*xr[0] + xr[1]*xr[1] + xr[2]*xr[2]);

    float acc[CC];

    {
        const float4* bq = (const float4*)b1v;
        #pragma unroll
        for (int c4 = 0; c4 < CC/4; c4++) {
            float4 bv = bq[c4];
            acc[c4*4+0]=bv.x; acc[c4*4+1]=bv.y; acc[c4*4+2]=bv.z; acc[c4*4+3]=bv.w;
        }
        #pragma unroll
        for (int d = 0; d < DD; d++) {
            float xv = xr[d];
            const float4* wv = (const float4*)(w1 + d*CC);
            #pragma unroll
            for (int c4 = 0; c4 < CC/4; c4++) {
                float4 w = wv[c4];
                acc[c4*4+0] = fmaf(xv, w.x, acc[c4*4+0]);
                acc[c4*4+1] = fmaf(xv, w.y, acc[c4*4+1]);
                acc[c4*4+2] = fmaf(xv, w.z, acc[c4*4+2]);
                acc[c4*4+3] = fmaf(xv, w.w, acc[c4*4+3]);
            }
        }
        #pragma unroll
        for (int c = 0; c < CC; c++) sh[c*256 + tid] = fmaxf(acc[c], 0.f);
    }

    {
        const float4* bq = (const float4*)g_c1;
        #pragma unroll
        for (int c4 = 0; c4 < CC/4; c4++) {
            float4 bv = bq[c4];
            acc[c4*4+0]=bv.x; acc[c4*4+1]=bv.y; acc[c4*4+2]=bv.z; acc[c4*4+3]=bv.w;
        }
        #pragma unroll 1
        for (int j = 0; j < CC; j++) {
            float hv = sh[j*256 + tid];
            const float4* wv = (const float4*)(g_C1 + j*CC);
            #pragma unroll
            for (int c4 = 0; c4 < CC/4; c4++) {
                float4 w = wv[c4];
                acc[c4*4+0] = fmaf(hv, w.x, acc[c4*4+0]);
                acc[c4*4+1] = fmaf(hv, w.y, acc[c4*4+1]);
                acc[c4*4+2] = fmaf(hv, w.z, acc[c4*4+2]);
                acc[c4*4+3] = fmaf(hv, w.w, acc[c4*4+3]);
            }
        }
        float4* o = (float4*)g_G1 + g*(CC/4);
        #pragma unroll
        for (int c4 = 0; c4 < CC/4; c4++)
            o[c4] = make_float4(acc[c4*4+0], acc[c4*4+1], acc[c4*4+2], acc[c4*4+3]);
    }

    {
        const float4* bq = (const float4*)g_c2;
        #pragma unroll
        for (int c4 = 0; c4 < CC/4; c4++) {
            float4 bv = bq[c4];
            acc[c4*4+0]=bv.x; acc[c4*4+1]=bv.y; acc[c4*4+2]=bv.z; acc[c4*4+3]=bv.w;
        }
        #pragma unroll 1
        for (int j = 0; j < CC; j++) {
            float hv = sh[j*256 + tid];
            const float4* wv = (const float4*)(g_C2 + j*CC);
            #pragma unroll
            for (int c4 = 0; c4 < CC/4; c4++) {
                float4 w = wv[c4];
                acc[c4*4+0] = fmaf(hv, w.x, acc[c4*4+0]);
                acc[c4*4+1] = fmaf(hv, w.y, acc[c4*4+1]);
                acc[c4*4+2] = fmaf(hv, w.z, acc[c4*4+2]);
                acc[c4*4+3] = fmaf(hv, w.w, acc[c4*4+3]);
            }
        }
        float4* o = (float4*)g_G2 + g*(CC/4);
        #pragma unroll
        for (int c4 = 0; c4 < CC/4; c4++)
            o[c4] = make_float4(acc[c4*4+0], acc[c4*4+1], acc[c4*4+2], acc[c4*4+3]);
    }
}

// ---------------------------------------------------------------------------
// Sort pass 1 (one block per batch): x min/max reduce, 256-bucket histogram,
// serial exclusive scan, write bucket starts/cursors/params.
// ---------------------------------------------------------------------------
__global__ __launch_bounds__(256) void sort1_kernel() {
    __shared__ float smn[256], smx[256];
    __shared__ int cnt[NB];
    __shared__ float sxmin, sinvw;
    int b = blockIdx.x, tid = threadIdx.x;

    float mn = inf_f(), mx = -inf_f();
    for (int j = tid; j < NN; j += 256) {
        float xv = g_pts[b*NN + j].x;
        mn = fminf(mn, xv); mx = fmaxf(mx, xv);
    }
    smn[tid] = mn; smx[tid] = mx;
    __syncthreads();
    for (int s = 128; s > 0; s >>= 1) {
        if (tid < s) {
            smn[tid] = fminf(smn[tid], smn[tid+s]);
            smx[tid] = fmaxf(smx[tid], smx[tid+s]);
        }
        __syncthreads();
    }
    if (tid == 0) {
        float xmin = smn[0], xmax = smx[0];
        float range = xmax - xmin;
        float w = range / (float)NB;
        sxmin = xmin;
        sinvw = (range > 0.f) ? ((float)NB / range) : 0.f;
        g_bparam[b] = make_float2(xmin, w);
    }
    cnt[tid] = 0;
    __syncthreads();

    for (int j = tid; j < NN; j += 256) {
        float xv = g_pts[b*NN + j].x;
        int bi = (int)((xv - sxmin) * sinvw);
        bi = bi < 0 ? 0 : (bi > NB-1 ? NB-1 : bi);
        atomicAdd(&cnt[bi], 1);
    }
    __syncthreads();

    if (tid == 0) {                       // serial scan (256 elems, cheap)
        int acc = 0;
        #pragma unroll 1
        for (int i = 0; i < NB; i++) {
            g_bstart[b][i] = acc;
            g_bcur[b][i] = acc;
            acc += cnt[i];
        }
        g_bstart[b][NB] = acc;            // = NN
    }
}

// ---------------------------------------------------------------------------
// Sort pass 2: scatter points into bucket order.
// ---------------------------------------------------------------------------
__global__ __launch_bounds__(256) void sort2_kernel() {
    int b = blockIdx.y;
    int j = blockIdx.x*256 + threadIdx.x;
    if (j >= NN) return;
    float2 bp = g_bparam[b];
    float invw = (bp.y > 0.f) ? (1.0f / bp.y) : 0.f;
    float4 c = g_pts[b*NN + j];
    int bi = (int)((c.x - bp.x) * invw);
    bi = bi < 0 ? 0 : (bi > NB-1 ? NB-1 : bi);
    int pos = atomicAdd(&g_bcur[b][bi], 1);
    g_sorted[b*NN + pos] = c;
    g_sidx[b*NN + pos] = j;
}

// ---------------------------------------------------------------------------
// Compaction: translate appended (dist_bits, sortedPos) to (dist_bits,
// origIdx) and insert into the 32 strided smem result slots (8x4 groups,
// group maxes in regs). u64 order == (dist, origIdx) == top_k order.
// ---------------------------------------------------------------------------
__device__ __noinline__ void compact_sorted(
    const int* __restrict__ sidx,
    unsigned long long* tslot, int& cnt,
    unsigned long long* gm, unsigned long long& worst, float& thr)
{
    #pragma unroll 1
    for (int a = 0; a < cnt; a++) {
        unsigned long long vp = tslot[(KK + a) * 256];
        int orig = sidx[(unsigned)vp];
        unsigned long long v = (vp & 0xFFFFFFFF00000000ull) | (unsigned)orig;
        if (v < worst) {
            int gsel = 0; unsigned long long gv = gm[0];
            #pragma unroll
            for (int i = 1; i < 8; i++) if (gm[i] > gv) { gv = gm[i]; gsel = i; }
            int base = gsel * 4;
            unsigned long long s0 = tslot[(base+0)*256];
            unsigned long long s1 = tslot[(base+1)*256];
            unsigned long long s2 = tslot[(base+2)*256];
            unsigned long long s3 = tslot[(base+3)*256];
            int e = 0; unsigned long long ev = s0;
            if (s1 > ev) { ev = s1; e = 1; }
            if (s2 > ev) { ev = s2; e = 2; }
            if (s3 > ev) { ev = s3; e = 3; }
            tslot[(base+e)*256] = v;
            unsigned long long n0 = (e==0)?v:s0, n1 = (e==1)?v:s1;
            unsigned long long n2 = (e==2)?v:s2, n3 = (e==3)?v:s3;
            unsigned long long m01 = n0 > n1 ? n0 : n1;
            unsigned long long m23 = n2 > n3 ? n2 : n3;
            unsigned long long ngm = m01 > m23 ? m01 : m23;
            #pragma unroll
            for (int i = 0; i < 8; i++) if (i == gsel) gm[i] = ngm;
            unsigned long long w8 = gm[0];
            #pragma unroll
            for (int i = 1; i < 8; i++) if (gm[i] > w8) w8 = gm[i];
            worst = w8;
        }
    }
    cnt = 0;
    thr = (worst == ~0ull) ? inf_f()
                           : __uint_as_float((unsigned)(worst >> 32));
}

// ---------------------------------------------------------------------------
// Exact 32-NN with x-bucket pruning (R16 + output-index FIX: results keyed by
// ORIGINAL point index sidx[spos], not sorted position). Query scans outward
// (4 right + 4 left per iter) from its sorted position; a side stops when the
// near edge of its current bucket satisfies (edge-dist - slack)^2 > thr.
// Same fma formula as R14 -> bit-identical selection. thr=INF until slots
// fill; <= appends keep boundary ties; compaction warp-synchronized.
// ---------------------------------------------------------------------------
__global__ __launch_bounds__(256) void knn_kernel() {
    extern __shared__ char smemraw[];
    int* bs_s = (int*)smemraw;                                // NB+1 ints
    unsigned long long* slots = (unsigned long long*)(smemraw + 1280);

    int tid = threadIdx.x;
    int b = blockIdx.y;
    const float4* gs = g_sorted + b*NN;
    const int* sidx = g_sidx + b*NN;

    for (int i = tid; i < NB+1; i += 256) bs_s[i] = g_bstart[b][i];
    __syncthreads();

    int spos = blockIdx.x*256 + tid;
    if (spos >= NN) spos = NN - 1;       // clamp (ballot safety; dup rows benign)

    float4 me = gs[spos];
    float qw = me.w, xq = me.x;
    float mx = -2.f*me.x, my = -2.f*me.y, mz = -2.f*me.z;
    float2 bp = g_bparam[b];
    float xmin = bp.x, w = bp.y;
    float slack = w * 0.01f;
    float invw = (w > 0.f) ? (1.0f / w) : 0.f;
    const float NANF = nan_f();

    unsigned long long* tslot = slots + tid;
    unsigned abase0;
    {
        unsigned long long l64;
        asm("cvta.to.shared.u64 %0, %1;" : "=l"(l64)
            : "l"((const void*)(tslot + KK*256)));
        abase0 = (unsigned)l64;
    }

    #pragma unroll
    for (int i = 0; i < KK; i++) tslot[i*256] = ~0ull;

    unsigned long long gm[8];
    #pragma unroll
    for (int i = 0; i < 8; i++) gm[i] = ~0ull;
    unsigned long long worst = ~0ull;
    float thr = inf_f();
    int cnt = 0;

    int bq = (int)((xq - xmin) * invw);
    bq = bq < 0 ? 0 : (bq > NB-1 ? NB-1 : bq);
    int R = spos, L = spos - 1;
    int rbi = bq, lbi = bq;

    #pragma unroll 1
    while (__any_sync(0xffffffffu, (R < NN) || (L >= 0))) {
        float s[8];
        int pos8[8];
        #pragma unroll
        for (int u = 0; u < 4; u++) {                        // right side
            int jr = R + u;
            int j = jr < NN ? jr : NN - 1;
            float4 c = gs[j];
            float ss = fmaf(c.x, mx, c.w + qw);
            ss = fmaf(c.y, my, ss);
            ss = fmaf(c.z, mz, ss);
            ss = fmaxf(ss, 0.f);
            s[u] = (jr < NN) ? ss : NANF;
            pos8[u] = j;
        }
        #pragma unroll
        for (int u = 0; u < 4; u++) {                        // left side
            int jl = L - u;
            int j = jl >= 0 ? jl : 0;
            float4 c = gs[j];
            float ss = fmaf(c.x, mx, c.w + qw);
            ss = fmaf(c.y, my, ss);
            ss = fmaf(c.z, mz, ss);
            ss = fmaxf(ss, 0.f);
            s[4+u] = (jl >= 0) ? ss : NANF;
            pos8[4+u] = j;
        }

        // predicates + tree-prefix offsets; predicated smem appends
        int e0 = (s[0] <= thr) ? 1 : 0;
        int e1 = (s[1] <= thr) ? 1 : 0;
        int e2 = (s[2] <= thr) ? 1 : 0;
        int e3 = (s[3] <= thr) ? 1 : 0;
        int e4 = (s[4] <= thr) ? 1 : 0;
        int e5 = (s[5] <= thr) ? 1 : 0;
        int e6 = (s[6] <= thr) ? 1 : 0;
        int e7 = (s[7] <= thr) ? 1 : 0;
        int t01 = e0+e1, t23 = e2+e3, t45 = e4+e5, t67 = e6+e7;
        int t03 = t01+t23, t47 = t45+t67;
        int o1 = e0, o2 = t01, o3 = t01+e2, o4 = t03;
        int o5 = t03+e4, o6 = t03+t45, o7 = t03+t45+e6;
        int tot = t03 + t47;
        unsigned rowa = abase0 + (unsigned)cnt * 2048u;
        #pragma unroll
        for (int u = 0; u < 8; u++) {
            int off;
            switch (u) {
                case 0: off = 0;  break;
                case 1: off = o1; break;
                case 2: off = o2; break;
                case 3: off = o3; break;
                case 4: off = o4; break;
                case 5: off = o5; break;
                case 6: off = o6; break;
                default: off = o7; break;
            }
            unsigned addr = rowa + (unsigned)off * 2048u;
            unsigned long long pk =
                ((unsigned long long)__float_as_uint(s[u]) << 32)
                | (unsigned)pos8[u];
            asm volatile(
                "{\n\t"
                ".reg .pred p;\n\t"
                "setp.le.f32 p, %0, %1;\n\t"
                "@p st.shared.b64 [%2], %3;\n\t"
                "}"
                :: "f"(s[u]), "f"(thr), "r"(addr), "l"(pk)
                : "memory");
        }
        cnt += tot;

        // advance cursors + bucket-edge termination
        if (R < NN) {
            R += 4;
            #pragma unroll 1
            while (rbi < NB-1 && R >= bs_s[rbi+1]) rbi++;
            float lb = fmaf((float)rbi, w, xmin) - xq - slack;
            if ((lb > 0.f && lb*lb > thr) || R > NN) R = NN;
        }
        if (L >= 0) {
            L -= 4;
            #pragma unroll 1
            while (lbi > 0 && L < bs_s[lbi]) lbi--;
            float lb = xq - fmaf((float)(lbi+1), w, xmin) - slack;
            if ((lb > 0.f && lb*lb > thr) || L < -1) L = -1;
        }

        if (__any_sync(0xffffffffu, cnt >= CAPA - 8)) {
            compact_sorted(sidx, tslot, cnt, gm, worst, thr);
        }
    }

    compact_sorted(sidx, tslot, cnt, gm, worst, thr);   // final flush

    // FIX: key the output row by the ORIGINAL point index of this query.
    int* o = g_idx + (b*NN + sidx[spos])*KK;
    #pragma unroll 1
    for (int i = 0; i < KK; i++)
        o[i] = (int)(unsigned)tslot[i*256];
}

// ---------------------------------------------------------------------------
// Fuse (both branches) + classifier.
// ---------------------------------------------------------------------------
__global__ __launch_bounds__(256) void fuse_kernel(
    const float* __restrict__ f1b, const float* __restrict__ f2b,
    const float* __restrict__ cw1, const float* __restrict__ cb1,
    const float* __restrict__ cw2, const float* __restrict__ cb2,
    float* __restrict__ out)
{
    __shared__ float sfused[4][CC];
    __shared__ float shid[4][CC/2];
    __shared__ int   sidx[4][KK];

    int tid = threadIdx.x;
    int p = tid >> 6, c = tid & 63;
    int g = blockIdx.x*4 + p;

    if (c < KK) sidx[p][c] = g_idx[g*KK + c];
    __syncthreads();

    int b = g / NN;
    int rowbase = b*NN;

    float g1i = g_G1[g*CC + c];
    float g2i = g_G2[g*CC + c];
    float bb1 = f1b[c] - g1i;
    float bb2 = f2b[c] - g2i;
    float m1 = 0.f, m2 = 0.f;
    #pragma unroll 8
    for (int k = 0; k < KK; k++) {
        int j = sidx[p][k] + rowbase;
        m1 = fmaxf(m1, g_G1[j*CC + c] + bb1);
        m2 = fmaxf(m2, g_G2[j*CC + c] + bb2);
    }
    sfused[p][c] = m1 + m2;
    __syncthreads();

    if (c < CC/2) {
        float a = cb1[c];
        #pragma unroll
        for (int u = 0; u < CC; u++) a = fmaf(sfused[p][u], cw1[u*(CC/2) + c], a);
        shid[p][c] = fmaxf(a, 0.f);
    }
    __syncthreads();

    if (c < NCLS) {
        float a = cb2[c];
        #pragma unroll
        for (int u = 0; u < CC/2; u++) a = fmaf(shid[p][u], cw2[u*NCLS + c], a);
        out[g*NCLS + c] = a;
    }
}

extern "C" void kernel_launch(void* const* d_in, const int* in_sizes, int n_in,
                              void* d_out, int out_size) {
    const float* x      = (const float*)d_in[0];
    const float* enc_w1 = (const float*)d_in[1];
    const float* enc_b1 = (const float*)d_in[2];
    const float* enc_w2 = (const float*)d_in[3];
    const float* enc_b2 = (const float*)d_in[4];
    const float* f1_w   = (const float*)d_in[5];
    const float* f1_b   = (const float*)d_in[6];
    const float* f2_w   = (const float*)d_in[7];
    const float* f2_b   = (const float*)d_in[8];
    const float* cls_w1 = (const float*)d_in[9];
    const float* cls_b1 = (const float*)d_in[10];
    const float* cls_w2 = (const float*)d_in[11];
    const float* cls_b2 = (const float*)d_in[12];

    precompute_kernel<<<(2*CC*CC + 2*CC + 255)/256, 256>>>(enc_w2, enc_b2,
                                                           f1_w, f2_w);

    const int enc_smem = CC * 256 * (int)sizeof(float);   // 65536
    cudaFuncSetAttribute(encoder_kernel,
                         cudaFuncAttributeMaxDynamicSharedMemorySize, enc_smem);
    encoder_kernel<<<(BN + 255)/256, 256, enc_smem>>>(x, enc_w1, enc_b1);

    sort1_kernel<<<BB, 256>>>();
    dim3 s2g((NN + 255)/256, BB);
    sort2_kernel<<<s2g, 256>>>();

    const int knn_smem = 1280 + NSLOT*256*8;   // 1280 + 180224 = 181504
    cudaFuncSetAttribute(knn_kernel, cudaFuncAttributeMaxDynamicSharedMemorySize,
                         knn_smem);
    dim3 kg((NN + 255)/256, BB);
    knn_kernel<<<kg, 256, knn_smem>>>();

    fuse_kernel<<<BN/4, 256>>>(f1_b, f2_b, cls_w1, cls_b1, cls_w2, cls_b2,
                               (float*)d_out);
}